// round 15
// baseline (speedup 1.0000x reference)
#include <cuda_runtime.h>
#include <cstdint>

#define TT   8192
#define HID  512
#define EE   256
#define ING  40
#define G0   64
#define G1   64

typedef unsigned long long ULL;

// ---------------- device scratch (static globals: no allocation) ------------
__device__ float g_xg0[TT * 2048];    // 64 MB: precomputed input gates, layer 0
__device__ ULL   g_th1[TT * HID];     // 32 MB: tagged h1 (L0 consumers ONLY)
__device__ ULL   g_th1x[TT * HID];    // 32 MB: tagged h1 copy (L1 consumers)
__device__ ULL   g_th2[TT * HID];     // 32 MB: tagged h2 history
__device__ float g_weff[2048 * ING];  // folded W_ih0 @ W_in
__device__ float g_beff[2048];        // folded bias
__device__ float g_cfin[2 * HID];     // final cell states

// ---------------- PTX helpers (morally strong tag ops) -----------------------
__device__ __forceinline__ ULL ld_rlx(const ULL* p) {
    ULL v;
    asm volatile("ld.relaxed.gpu.global.b64 %0, [%1];" : "=l"(v) : "l"(p) : "memory");
    return v;
}
__device__ __forceinline__ void st_rlx(ULL* p, ULL v) {
    asm volatile("st.relaxed.gpu.global.b64 [%0], %1;" :: "l"(p), "l"(v) : "memory");
}
__device__ __forceinline__ ULL fma2(ULL a, ULL b, ULL c) {
    ULL d;
    asm("fma.rn.f32x2 %0, %1, %2, %3;" : "=l"(d) : "l"(a), "l"(b), "l"(c));
    return d;
}
__device__ __forceinline__ ULL add2(ULL a, ULL b) {
    ULL d;
    asm("add.rn.f32x2 %0, %1, %2;" : "=l"(d) : "l"(a), "l"(b));
    return d;
}
__device__ __forceinline__ void unpack2(ULL v, float& lo, float& hi) {
    asm("mov.b64 {%0, %1}, %2;" : "=f"(lo), "=f"(hi) : "l"(v));
}
__device__ __forceinline__ float tanh_apx(float x) {
    float y; asm("tanh.approx.f32 %0, %1;" : "=f"(y) : "f"(x)); return y;
}
__device__ __forceinline__ float sig_apx(float x) {
    return fmaf(0.5f, tanh_apx(0.5f * x), 0.5f);
}

// ---------------- clear tag arrays (must run every launch / replay) ---------
__global__ void k_clear() {
    size_t i = (size_t)blockIdx.x * blockDim.x + threadIdx.x;
    ulonglong2 z = make_ulonglong2(0ull, 0ull);
    ((ulonglong2*)g_th1)[i]  = z;
    ((ulonglong2*)g_th1x)[i] = z;
    ((ulonglong2*)g_th2)[i]  = z;
}

// ---------------- fold input projection into layer-0 input weights ----------
__global__ void k_fold(const float* __restrict__ W_ih0, const float* __restrict__ W_in,
                       const float* __restrict__ b_in,  const float* __restrict__ b_ih0,
                       const float* __restrict__ b_hh0) {
    __shared__ float srow[EE];
    int j = blockIdx.x;
    for (int e = threadIdx.x; e < EE; e += 64) srow[e] = W_ih0[(size_t)j * EE + e];
    __syncthreads();
    if (threadIdx.x < ING) {
        int i = threadIdx.x;
        float s = 0.f;
        #pragma unroll 8
        for (int e = 0; e < EE; ++e) s += srow[e] * W_in[e * ING + i];
        g_weff[(size_t)j * ING + i] = s;
    } else if (threadIdx.x == ING) {
        float s = 0.f;
        #pragma unroll 8
        for (int e = 0; e < EE; ++e) s += srow[e] * b_in[e];
        g_beff[j] = s + b_ih0[j] + b_hh0[j];
    }
}

// ---------------- precompute xg0[t][j] = in_states[t] @ Weff[j] + beff[j] ---
__global__ void k_xg0(const float* __restrict__ in_states) {
    __shared__ float s_in[16 * ING];
    const int t0 = blockIdx.y * 16;
    const int j  = blockIdx.x * 256 + threadIdx.x;
    for (int idx = threadIdx.x; idx < 16 * ING; idx += 256)
        s_in[idx] = in_states[(size_t)t0 * ING + idx];
    __syncthreads();

    float wreg[ING];
    const float4* wp = (const float4*)(g_weff + (size_t)j * ING);
    #pragma unroll
    for (int u = 0; u < ING / 4; ++u) ((float4*)wreg)[u] = wp[u];

    float acc[16];
    float b = g_beff[j];
    #pragma unroll
    for (int tt = 0; tt < 16; ++tt) acc[tt] = b;
    #pragma unroll
    for (int i = 0; i < ING; ++i) {
        float wv = wreg[i];
        #pragma unroll
        for (int tt = 0; tt < 16; ++tt) acc[tt] += wv * s_in[tt * ING + i];
    }
    #pragma unroll
    for (int tt = 0; tt < 16; ++tt)
        g_xg0[(size_t)(t0 + tt) * 2048 + j] = acc[tt];
}

// ---------------- persistent recurrent kernel: both LSTM layers -------------
// blocks 0..63: layer 0;  blocks 64..127: layer 1.  (R14 base)
// L1 never feeds back into L0 -> total time = TT * P(L0) + const; only L0's
// publish->detect loop matters. Contention control on the PACING lines:
//   (a) DUAL PUBLISH: L0 writes h1 to g_th1 (polled by L0 only) and g_th1x
//       (polled by L1 only) -> zero cross-layer same-line poll interference.
//   (b) L1's h1 spin keeps the __nanosleep throttle (R14 win), h2 spin plain.
__global__ void __launch_bounds__(512, 1) k_rec(
    const float* __restrict__ W_hh0, const float* __restrict__ W_ih1,
    const float* __restrict__ W_hh1, const float* __restrict__ b_ih1,
    const float* __restrict__ b_hh1) {
    __shared__ __align__(16) float sh1[HID];        // L1: h1[t] slices
    __shared__ __align__(16) float sh2[HID];        // recurrent h(t-1) slices
    __shared__ __align__(16) float part[2][512];

    const int  tid  = threadIdx.x;
    const int  w    = tid >> 5;
    const int  r    = tid & 31;
    const bool isL0 = (blockIdx.x < G0);
    const int  cl   = isL0 ? blockIdx.x : (blockIdx.x - G0);
    const int  m0   = cl * 8;
    const int  q    = r >> 3, ml = r & 7;
    const int  grow = q * 512 + m0 + ml;            // global gate row

    // weights in registers, packed f32x2
    ULL wa[16];
    {
        const ULL* pa = (const ULL*)((isL0 ? W_hh0 : W_hh1) + (size_t)grow * HID + w * 32);
        #pragma unroll
        for (int u = 0; u < 16; ++u) wa[u] = pa[u];
    }
    ULL wb[16];
    if (!isL0) {
        const ULL* pb = (const ULL*)(W_ih1 + (size_t)grow * HID + w * 32);
        #pragma unroll
        for (int u = 0; u < 16; ++u) wb[u] = pb[u];
    }
    const float bias_c = isL0 ? 0.f : (b_ih1[grow] + b_hh1[grow]);

    ULL* trec = isL0 ? g_th1 : g_th2;    // own recurrent stream (read t-1, write t)

    // rolling poll/publish pointers
    const ULL* pA    = g_th1x + (size_t)w * 32 + r;               // h1[t], L1 only
    const ULL* pB    = trec - HID + (size_t)w * 32 + r;           // h(t-1)
    ULL*       pPub  = trec + (size_t)m0 + r;                     // warp0 lanes r<8
    ULL*       pPubX = g_th1x + (size_t)m0 + r;                   // L0 dual publish

    float creg = 0.f;
    float xg_next = 0.f, xg_next2 = 0.f;
    if (isL0 && w == 0) {
        xg_next  = __ldcg(&g_xg0[grow]);                      // t = 0
        xg_next2 = __ldcg(&g_xg0[2048 + grow]);               // t = 1
    }

    for (int t = 0; t < TT; ++t) {
        // ---- issue BOTH dependency loads immediately (overlapped RTs) ----
        ULL va = 0, vb = 0;
        if (!isL0)  va = ld_rlx(pA);
        if (t > 0)  vb = ld_rlx(pB);

        float xg_cur = xg_next;
        xg_next = xg_next2;
        if (isL0 && w == 0 && t + 2 < TT)
            xg_next2 = __ldcg(&g_xg0[(size_t)(t + 2) * 2048 + grow]);

        ULL a0 = 0, a1 = 0, a2 = 0, a3 = 0;

        // ---- L1: consume h1[t] (THROTTLED spin — latency-insensitive), ----
        // ---- then the W_ih1 half while the h2 load is in flight.        ----
        if (!isL0) {
            const unsigned wantA = (unsigned)(t + 1);
            while ((unsigned)(va >> 32) != wantA) {
                __nanosleep(350);                 // burn L1 slack, not L2 slots
                va = ld_rlx(pA);
            }
            sh1[w * 32 + r] = __uint_as_float((unsigned)va);
            __syncwarp();
            const ULL* hp = (const ULL*)(sh1 + w * 32);
            #pragma unroll
            for (int u = 0; u < 4; ++u) {
                a0 = fma2(wb[4 * u + 0], hp[4 * u + 0], a0);
                a1 = fma2(wb[4 * u + 1], hp[4 * u + 1], a1);
                a2 = fma2(wb[4 * u + 2], hp[4 * u + 2], a2);
                a3 = fma2(wb[4 * u + 3], hp[4 * u + 3], a3);
            }
        }

        // ---- critical wait: dependent spin on h(t-1) (load already in flight)
        if (t > 0) {
            const unsigned wantB = (unsigned)t;
            while ((unsigned)(vb >> 32) != wantB) vb = ld_rlx(pB);
            sh2[w * 32 + r] = __uint_as_float((unsigned)vb);
        } else {
            sh2[w * 32 + r] = 0.f;
        }
        __syncwarp();
        {
            const ULL* hq = (const ULL*)(sh2 + w * 32);
            #pragma unroll
            for (int u = 0; u < 4; ++u) {
                a0 = fma2(wa[4 * u + 0], hq[4 * u + 0], a0);
                a1 = fma2(wa[4 * u + 1], hq[4 * u + 1], a1);
                a2 = fma2(wa[4 * u + 2], hq[4 * u + 2], a2);
                a3 = fma2(wa[4 * u + 3], hq[4 * u + 3], a3);
            }
        }
        {
            ULL s = add2(add2(a0, a1), add2(a2, a3));
            float alo, ahi; unpack2(s, alo, ahi);
            part[t & 1][w * 32 + r] = alo + ahi;
        }
        __syncthreads();   // the only CTA-wide barrier per step

        // ---- warp 0: reduce, per-lane activation, shuffle, cell update ----
        if (w == 0) {
            const float* pbuf = part[t & 1];
            float v[16];
            #pragma unroll
            for (int u = 0; u < 16; ++u) v[u] = pbuf[u * 32 + r];
            float s0 = (v[0] + v[1]) + (v[2] + v[3]);
            float s1 = (v[4] + v[5]) + (v[6] + v[7]);
            float s2 = (v[8] + v[9]) + (v[10] + v[11]);
            float s3 = (v[12] + v[13]) + (v[14] + v[15]);
            float s  = ((s0 + s1) + (s2 + s3)) + (isL0 ? xg_cur : bias_c);

            // activation in ALL lanes first (q==2 -> tanh gate, else sigmoid)
            float act = (q == 2) ? tanh_apx(s) : sig_apx(s);
            float pi = __shfl_sync(0xffffffffu, act, ml);
            float pf = __shfl_sync(0xffffffffu, act, 8 + ml);
            float pg = __shfl_sync(0xffffffffu, act, 16 + ml);
            float po = __shfl_sync(0xffffffffu, act, 24 + ml);
            if (r < 8) {
                creg = pf * creg + pi * pg;
                float h = po * tanh_apx(creg);
                ULL word = ((ULL)(unsigned)(t + 1) << 32) | (ULL)__float_as_uint(h);
                st_rlx(pPub, word);             // pacing copy (L0 pollers)
                if (isL0) st_rlx(pPubX, word);  // L1-consumer copy
            }
        }
        pA += HID; pB += HID; pPub += HID; pPubX += HID;
    }

    if (w == 0 && r < 8) g_cfin[(isL0 ? 0 : HID) + m0 + r] = creg;
}

// ---------------- output projection + final states --------------------------
__global__ void k_out(const float* __restrict__ W_out, const float* __restrict__ b_out,
                      float* __restrict__ out, int out_size) {
    int wid = threadIdx.x >> 5, lane = threadIdx.x & 31;
    int t = blockIdx.x * 8 + wid;
    float acc = 0.f;
    #pragma unroll
    for (int j = 0; j < 16; ++j) {
        int k = j * 32 + lane;
        acc += __uint_as_float((unsigned)g_th2[(size_t)t * HID + k]) * W_out[k];
    }
    #pragma unroll
    for (int o = 16; o; o >>= 1) acc += __shfl_down_sync(0xffffffffu, acc, o);
    if (lane == 0 && t < out_size) out[t] = acc + b_out[0];

    if (blockIdx.x == 0 && out_size >= TT + 2048) {
        for (int i = threadIdx.x; i < 512; i += 256) {
            out[TT + i]        = __uint_as_float((unsigned)g_th1[(size_t)(TT - 1) * HID + i]);
            out[TT + 512 + i]  = __uint_as_float((unsigned)g_th2[(size_t)(TT - 1) * HID + i]);
            out[TT + 1024 + i] = g_cfin[i];
            out[TT + 1536 + i] = g_cfin[512 + i];
        }
    }
}

// ---------------- launch -----------------------------------------------------
extern "C" void kernel_launch(void* const* d_in, const int* in_sizes, int n_in,
                              void* d_out, int out_size) {
    const float* in_states = (const float*)d_in[0];
    const float* W_in  = (const float*)d_in[1];
    const float* b_in  = (const float*)d_in[2];
    const float* W_ih0 = (const float*)d_in[3];
    const float* W_hh0 = (const float*)d_in[4];
    const float* b_ih0 = (const float*)d_in[5];
    const float* b_hh0 = (const float*)d_in[6];
    const float* W_ih1 = (const float*)d_in[7];
    const float* W_hh1 = (const float*)d_in[8];
    const float* b_ih1 = (const float*)d_in[9];
    const float* b_hh1 = (const float*)d_in[10];
    const float* W_out = (const float*)d_in[11];
    const float* b_out = (const float*)d_in[12];

    k_clear<<<2048, 1024>>>();
    k_fold<<<2048, 64>>>(W_ih0, W_in, b_in, b_ih0, b_hh0);
    k_xg0<<<dim3(2048 / 256, TT / 16), 256>>>(in_states);
    k_rec<<<G0 + G1, 512>>>(W_hh0, W_ih1, W_hh1, b_ih1, b_hh1);
    k_out<<<TT / 8, 256>>>(W_out, b_out, (float*)d_out, out_size);
}

// round 16
// speedup vs baseline: 1.0461x; 1.0461x over previous
#include <cuda_runtime.h>
#include <cstdint>

#define TT   8192
#define HID  512
#define EE   256
#define ING  40
#define G0   64
#define G1   64

typedef unsigned long long ULL;

// ---------------- device scratch (static globals: no allocation) ------------
__device__ float g_xg0[TT * 2048];    // 64 MB: precomputed input gates, layer 0
__device__ ULL   g_th1[TT * HID];     // 32 MB: tagged h1 (L0 pacing consumers)
__device__ ULL   g_th1x[TT * HID];    // 32 MB: tagged h1 copy (L1 consumers)
__device__ ULL   g_th2[TT * HID];     // 32 MB: tagged h2 history
__device__ float g_weff[2048 * ING];  // folded W_ih0 @ W_in
__device__ float g_beff[2048];        // folded bias
__device__ float g_cfin[2 * HID];     // final cell states

// ---------------- PTX helpers (morally strong tag ops) -----------------------
__device__ __forceinline__ ULL ld_rlx(const ULL* p) {
    ULL v;
    asm volatile("ld.relaxed.gpu.global.b64 %0, [%1];" : "=l"(v) : "l"(p) : "memory");
    return v;
}
__device__ __forceinline__ void st_rlx(ULL* p, ULL v) {
    asm volatile("st.relaxed.gpu.global.b64 [%0], %1;" :: "l"(p), "l"(v) : "memory");
}
__device__ __forceinline__ ULL fma2(ULL a, ULL b, ULL c) {
    ULL d;
    asm("fma.rn.f32x2 %0, %1, %2, %3;" : "=l"(d) : "l"(a), "l"(b), "l"(c));
    return d;
}
__device__ __forceinline__ ULL add2(ULL a, ULL b) {
    ULL d;
    asm("add.rn.f32x2 %0, %1, %2;" : "=l"(d) : "l"(a), "l"(b));
    return d;
}
__device__ __forceinline__ void unpack2(ULL v, float& lo, float& hi) {
    asm("mov.b64 {%0, %1}, %2;" : "=f"(lo), "=f"(hi) : "l"(v));
}
__device__ __forceinline__ float tanh_apx(float x) {
    float y; asm("tanh.approx.f32 %0, %1;" : "=f"(y) : "f"(x)); return y;
}
__device__ __forceinline__ float sig_apx(float x) {
    return fmaf(0.5f, tanh_apx(0.5f * x), 0.5f);
}

// ---------------- clear tag arrays (must run every launch / replay) ---------
__global__ void k_clear() {
    size_t i = (size_t)blockIdx.x * blockDim.x + threadIdx.x;
    ulonglong2 z = make_ulonglong2(0ull, 0ull);
    ((ulonglong2*)g_th1)[i]  = z;
    ((ulonglong2*)g_th1x)[i] = z;
    ((ulonglong2*)g_th2)[i]  = z;
}

// ---------------- fold input projection into layer-0 input weights ----------
__global__ void k_fold(const float* __restrict__ W_ih0, const float* __restrict__ W_in,
                       const float* __restrict__ b_in,  const float* __restrict__ b_ih0,
                       const float* __restrict__ b_hh0) {
    __shared__ float srow[EE];
    int j = blockIdx.x;
    for (int e = threadIdx.x; e < EE; e += 64) srow[e] = W_ih0[(size_t)j * EE + e];
    __syncthreads();
    if (threadIdx.x < ING) {
        int i = threadIdx.x;
        float s = 0.f;
        #pragma unroll 8
        for (int e = 0; e < EE; ++e) s += srow[e] * W_in[e * ING + i];
        g_weff[(size_t)j * ING + i] = s;
    } else if (threadIdx.x == ING) {
        float s = 0.f;
        #pragma unroll 8
        for (int e = 0; e < EE; ++e) s += srow[e] * b_in[e];
        g_beff[j] = s + b_ih0[j] + b_hh0[j];
    }
}

// ---------------- precompute xg0[t][j] = in_states[t] @ Weff[j] + beff[j] ---
__global__ void k_xg0(const float* __restrict__ in_states) {
    __shared__ float s_in[16 * ING];
    const int t0 = blockIdx.y * 16;
    const int j  = blockIdx.x * 256 + threadIdx.x;
    for (int idx = threadIdx.x; idx < 16 * ING; idx += 256)
        s_in[idx] = in_states[(size_t)t0 * ING + idx];
    __syncthreads();

    float wreg[ING];
    const float4* wp = (const float4*)(g_weff + (size_t)j * ING);
    #pragma unroll
    for (int u = 0; u < ING / 4; ++u) ((float4*)wreg)[u] = wp[u];

    float acc[16];
    float b = g_beff[j];
    #pragma unroll
    for (int tt = 0; tt < 16; ++tt) acc[tt] = b;
    #pragma unroll
    for (int i = 0; i < ING; ++i) {
        float wv = wreg[i];
        #pragma unroll
        for (int tt = 0; tt < 16; ++tt) acc[tt] += wv * s_in[tt * ING + i];
    }
    #pragma unroll
    for (int tt = 0; tt < 16; ++tt)
        g_xg0[(size_t)(t0 + tt) * 2048 + j] = acc[tt];
}

// ---------------- persistent recurrent kernel: both LSTM layers -------------
// blocks 0..63: layer 0;  blocks 64..127: layer 1.  (R14 base)
// L1 never feeds back into L0 -> total time = TT * P(L0) + const. Contention
// control on the pacing (g_th1) lines:
//   (a) L0 warp0 publishes ONLY the pacing copy (g_th1, polled by L0).
//   (b) L0 warp1 runs a SHADOW TAIL: identical deterministic reduce/act/cell
//       (own bit-identical creg) and publishes g_th1x for L1's consumers —
//       zero added cost on the critical chain (warp1 was idle).
//   (c) L1's h1 spin polls g_th1x with the __nanosleep throttle (R14 win).
__global__ void __launch_bounds__(512, 1) k_rec(
    const float* __restrict__ W_hh0, const float* __restrict__ W_ih1,
    const float* __restrict__ W_hh1, const float* __restrict__ b_ih1,
    const float* __restrict__ b_hh1) {
    __shared__ __align__(16) float sh1[HID];        // L1: h1[t] slices
    __shared__ __align__(16) float sh2[HID];        // recurrent h(t-1) slices
    __shared__ __align__(16) float part[2][512];

    const int  tid  = threadIdx.x;
    const int  w    = tid >> 5;
    const int  r    = tid & 31;
    const bool isL0 = (blockIdx.x < G0);
    const int  cl   = isL0 ? blockIdx.x : (blockIdx.x - G0);
    const int  m0   = cl * 8;
    const int  q    = r >> 3, ml = r & 7;
    const int  grow = q * 512 + m0 + ml;            // global gate row

    // weights in registers, packed f32x2
    ULL wa[16];
    {
        const ULL* pa = (const ULL*)((isL0 ? W_hh0 : W_hh1) + (size_t)grow * HID + w * 32);
        #pragma unroll
        for (int u = 0; u < 16; ++u) wa[u] = pa[u];
    }
    ULL wb[16];
    if (!isL0) {
        const ULL* pb = (const ULL*)(W_ih1 + (size_t)grow * HID + w * 32);
        #pragma unroll
        for (int u = 0; u < 16; ++u) wb[u] = pb[u];
    }
    const float bias_c = isL0 ? 0.f : (b_ih1[grow] + b_hh1[grow]);

    ULL* trec = isL0 ? g_th1 : g_th2;    // own recurrent stream (read t-1, write t)

    // rolling poll/publish pointers
    const ULL* pA    = g_th1x + (size_t)w * 32 + r;               // h1[t], L1 only
    const ULL* pB    = trec - HID + (size_t)w * 32 + r;           // h(t-1)
    ULL*       pPub  = trec + (size_t)m0 + r;                     // warp0 lanes r<8
    ULL*       pPubX = g_th1x + (size_t)m0 + r;                   // warp1 (L0 only)

    // does this warp run a tail? warp0 always; warp1 only in L0 (shadow)
    const bool tail0 = (w == 0);
    const bool tail1 = (w == 1) && isL0;

    float creg = 0.f;                    // carried identically in warp0 & warp1
    float xg_next = 0.f, xg_next2 = 0.f;
    if (isL0 && w < 2) {
        xg_next  = __ldcg(&g_xg0[grow]);                      // t = 0
        xg_next2 = __ldcg(&g_xg0[2048 + grow]);               // t = 1
    }

    for (int t = 0; t < TT; ++t) {
        // ---- issue BOTH dependency loads immediately (overlapped RTs) ----
        ULL va = 0, vb = 0;
        if (!isL0)  va = ld_rlx(pA);
        if (t > 0)  vb = ld_rlx(pB);

        float xg_cur = xg_next;
        xg_next = xg_next2;
        if (isL0 && w < 2 && t + 2 < TT)
            xg_next2 = __ldcg(&g_xg0[(size_t)(t + 2) * 2048 + grow]);

        ULL a0 = 0, a1 = 0, a2 = 0, a3 = 0;

        // ---- L1: consume h1[t] (THROTTLED spin — latency-insensitive), ----
        // ---- then the W_ih1 half while the h2 load is in flight.        ----
        if (!isL0) {
            const unsigned wantA = (unsigned)(t + 1);
            while ((unsigned)(va >> 32) != wantA) {
                __nanosleep(350);                 // burn L1 slack, not L2 slots
                va = ld_rlx(pA);
            }
            sh1[w * 32 + r] = __uint_as_float((unsigned)va);
            __syncwarp();
            const ULL* hp = (const ULL*)(sh1 + w * 32);
            #pragma unroll
            for (int u = 0; u < 4; ++u) {
                a0 = fma2(wb[4 * u + 0], hp[4 * u + 0], a0);
                a1 = fma2(wb[4 * u + 1], hp[4 * u + 1], a1);
                a2 = fma2(wb[4 * u + 2], hp[4 * u + 2], a2);
                a3 = fma2(wb[4 * u + 3], hp[4 * u + 3], a3);
            }
        }

        // ---- critical wait: dependent spin on h(t-1) (load already in flight)
        if (t > 0) {
            const unsigned wantB = (unsigned)t;
            while ((unsigned)(vb >> 32) != wantB) vb = ld_rlx(pB);
            sh2[w * 32 + r] = __uint_as_float((unsigned)vb);
        } else {
            sh2[w * 32 + r] = 0.f;
        }
        __syncwarp();
        {
            const ULL* hq = (const ULL*)(sh2 + w * 32);
            #pragma unroll
            for (int u = 0; u < 4; ++u) {
                a0 = fma2(wa[4 * u + 0], hq[4 * u + 0], a0);
                a1 = fma2(wa[4 * u + 1], hq[4 * u + 1], a1);
                a2 = fma2(wa[4 * u + 2], hq[4 * u + 2], a2);
                a3 = fma2(wa[4 * u + 3], hq[4 * u + 3], a3);
            }
        }
        {
            ULL s = add2(add2(a0, a1), add2(a2, a3));
            float alo, ahi; unpack2(s, alo, ahi);
            part[t & 1][w * 32 + r] = alo + ahi;
        }
        __syncthreads();   // the only CTA-wide barrier per step

        // ---- tails: warp0 (pacing publish) and warp1 (shadow publish, L0) --
        if (tail0 || tail1) {
            const float* pbuf = part[t & 1];
            float v[16];
            #pragma unroll
            for (int u = 0; u < 16; ++u) v[u] = pbuf[u * 32 + r];
            float s0 = (v[0] + v[1]) + (v[2] + v[3]);
            float s1 = (v[4] + v[5]) + (v[6] + v[7]);
            float s2 = (v[8] + v[9]) + (v[10] + v[11]);
            float s3 = (v[12] + v[13]) + (v[14] + v[15]);
            float s  = ((s0 + s1) + (s2 + s3)) + (isL0 ? xg_cur : bias_c);

            // activation in ALL lanes first (q==2 -> tanh gate, else sigmoid)
            float act = (q == 2) ? tanh_apx(s) : sig_apx(s);
            float pi = __shfl_sync(0xffffffffu, act, ml);
            float pf = __shfl_sync(0xffffffffu, act, 8 + ml);
            float pg = __shfl_sync(0xffffffffu, act, 16 + ml);
            float po = __shfl_sync(0xffffffffu, act, 24 + ml);
            if (r < 8) {
                creg = pf * creg + pi * pg;
                float h = po * tanh_apx(creg);
                ULL word = ((ULL)(unsigned)(t + 1) << 32) | (ULL)__float_as_uint(h);
                if (w == 0) st_rlx(pPub,  word);   // pacing copy (L0/L2 stream)
                else        st_rlx(pPubX, word);   // shadow copy for L1 pollers
            }
        }
        pA += HID; pB += HID; pPub += HID; pPubX += HID;
    }

    if (w == 0 && r < 8) g_cfin[(isL0 ? 0 : HID) + m0 + r] = creg;
}

// ---------------- output projection + final states --------------------------
__global__ void k_out(const float* __restrict__ W_out, const float* __restrict__ b_out,
                      float* __restrict__ out, int out_size) {
    int wid = threadIdx.x >> 5, lane = threadIdx.x & 31;
    int t = blockIdx.x * 8 + wid;
    float acc = 0.f;
    #pragma unroll
    for (int j = 0; j < 16; ++j) {
        int k = j * 32 + lane;
        acc += __uint_as_float((unsigned)g_th2[(size_t)t * HID + k]) * W_out[k];
    }
    #pragma unroll
    for (int o = 16; o; o >>= 1) acc += __shfl_down_sync(0xffffffffu, acc, o);
    if (lane == 0 && t < out_size) out[t] = acc + b_out[0];

    if (blockIdx.x == 0 && out_size >= TT + 2048) {
        for (int i = threadIdx.x; i < 512; i += 256) {
            out[TT + i]        = __uint_as_float((unsigned)g_th1[(size_t)(TT - 1) * HID + i]);
            out[TT + 512 + i]  = __uint_as_float((unsigned)g_th2[(size_t)(TT - 1) * HID + i]);
            out[TT + 1024 + i] = g_cfin[i];
            out[TT + 1536 + i] = g_cfin[512 + i];
        }
    }
}

// ---------------- launch -----------------------------------------------------
extern "C" void kernel_launch(void* const* d_in, const int* in_sizes, int n_in,
                              void* d_out, int out_size) {
    const float* in_states = (const float*)d_in[0];
    const float* W_in  = (const float*)d_in[1];
    const float* b_in  = (const float*)d_in[2];
    const float* W_ih0 = (const float*)d_in[3];
    const float* W_hh0 = (const float*)d_in[4];
    const float* b_ih0 = (const float*)d_in[5];
    const float* b_hh0 = (const float*)d_in[6];
    const float* W_ih1 = (const float*)d_in[7];
    const float* W_hh1 = (const float*)d_in[8];
    const float* b_ih1 = (const float*)d_in[9];
    const float* b_hh1 = (const float*)d_in[10];
    const float* W_out = (const float*)d_in[11];
    const float* b_out = (const float*)d_in[12];

    k_clear<<<2048, 1024>>>();
    k_fold<<<2048, 64>>>(W_ih0, W_in, b_in, b_ih0, b_hh0);
    k_xg0<<<dim3(2048 / 256, TT / 16), 256>>>(in_states);
    k_rec<<<G0 + G1, 512>>>(W_hh0, W_ih1, W_hh1, b_ih1, b_hh1);
    k_out<<<TT / 8, 256>>>(W_out, b_out, (float*)d_out, out_size);
}